// round 9
// baseline (speedup 1.0000x reference)
#include <cuda_runtime.h>
#include <cstdint>

// KVGather: out[n,i,k,w,c] = r_weight[n,i,k] * kv[n, r_idx[n,i,k], w, c]
// N=16, P2=64, TOPK=8, W2=64, C_KV=512
// 1.074 GiB compulsory write + ~74 MB kv read spill; at the traffic floor.
// Proven path (R8): 128-bit nc loads + L2::evict_last hint, evict-first
// streaming stores @ 6631 GB/s (83.6% DRAM).
// R9 single change: 256-bit stores (st.global.L2::cache_hint.v8.b32 with an
// explicit evict_first policy) — halve store-issue/wavefront count for the
// dominant write stream. Loads untouched.

#define KVG_N     16
#define KVG_P2    64
#define KVG_TOPK  8
#define KVG_W2    64
#define KVG_CKV   512

#define NUM_TILES   (KVG_N * KVG_P2 * KVG_TOPK)      // 8192
#define TILE_F4     (KVG_W2 * KVG_CKV / 4)           // 8192 float4 per tile (128 KB)
#define F4_PER_THR  8
#define THREADS     256
#define F4_PER_BLK  (F4_PER_THR * THREADS)           // 2048
#define BLKS_PER_TILE (TILE_F4 / F4_PER_BLK)         // 4
#define GRID        (NUM_TILES * BLKS_PER_TILE)      // 32768

__device__ __forceinline__ float4 ldg_l2el(const float4* p, uint64_t pol) {
    float4 v;
    asm("ld.global.nc.L2::cache_hint.v4.f32 {%0,%1,%2,%3}, [%4], %5;"
        : "=f"(v.x), "=f"(v.y), "=f"(v.z), "=f"(v.w)
        : "l"(p), "l"(pol));
    return v;
}

// 256-bit store with evict-first L2 policy (streaming write).
__device__ __forceinline__ void stg256_ef(float4* p, float4 a, float4 b,
                                          uint64_t pol) {
    asm volatile("st.global.L2::cache_hint.v8.f32 [%0], "
                 "{%1,%2,%3,%4,%5,%6,%7,%8}, %9;"
                 :: "l"(p),
                    "f"(a.x), "f"(a.y), "f"(a.z), "f"(a.w),
                    "f"(b.x), "f"(b.y), "f"(b.z), "f"(b.w),
                    "l"(pol)
                 : "memory");
}

__global__ __launch_bounds__(THREADS, 8)
void kvg_gather_kernel(const float4* __restrict__ kv,
                       const float*  __restrict__ r_weight,
                       const void*   __restrict__ r_idx,
                       float4*       __restrict__ out) {
    const int bid   = blockIdx.x;
    const int tile  = bid >> 2;            // BLKS_PER_TILE = 4
    const int chunk = bid & 3;
    const int n     = tile >> 9;           // / (P2*TOPK)

    // ---- int64-vs-int32 index-width detection, fused in-kernel ----
    // int64 values in [0,64) -> every odd 32-bit word 0; int32 indices ->
    // OR of 32 odd words nonzero w.p. 1-(1/64)^32. Words [1..63] are
    // in-bounds for both layouts; sectors are L2-hot.
    const int lane = threadIdx.x & 31;
    unsigned probe = ((const unsigned*)r_idx)[2 * lane + 1];
    unsigned odd_or = __reduce_or_sync(0xffffffffu, probe);
    const bool is64 = (odd_or == 0u);

    long long idx;
    if (is64) idx = ((const long long*)r_idx)[tile];
    else      idx = (long long)((const int*)r_idx)[tile];

    const float wt = r_weight[tile];

    uint64_t pol_el, pol_ef;
    asm("createpolicy.fractional.L2::evict_last.b64 %0, 1.0;"  : "=l"(pol_el));
    asm("createpolicy.fractional.L2::evict_first.b64 %0, 1.0;" : "=l"(pol_ef));

    const float4* __restrict__ src =
        kv + ((long long)n * KVG_P2 + idx) * (long long)TILE_F4;
    float4* __restrict__ dst = out + (long long)tile * (long long)TILE_F4;

    // Pair consecutive j so each thread's two float4 are 16B-adjacent:
    // thread covers float4 indices {base2, base2+1} per iteration -> one
    // 32-byte store. Warp still covers 1 KB contiguous per store op.
    const int base2 = chunk * F4_PER_BLK + 2 * threadIdx.x;

#pragma unroll
    for (int j = 0; j < F4_PER_THR / 2; j++) {
        const int p = base2 + j * (2 * THREADS);
        float4 a = ldg_l2el(&src[p],     pol_el);
        float4 b = ldg_l2el(&src[p + 1], pol_el);
        a.x *= wt; a.y *= wt; a.z *= wt; a.w *= wt;
        b.x *= wt; b.y *= wt; b.z *= wt; b.w *= wt;
        stg256_ef(&dst[p], a, b, pol_ef);
    }
}

extern "C" void kernel_launch(void* const* d_in, const int* in_sizes, int n_in,
                              void* d_out, int out_size) {
    // metadata order: r_idx, r_weight, kv
    const void*  r_idx    = d_in[0];
    const float* r_weight = (const float*)d_in[1];
    const float4* kv      = (const float4*)d_in[2];
    float4* out           = (float4*)d_out;

    kvg_gather_kernel<<<GRID, THREADS>>>(kv, r_weight, r_idx, out);
}